// round 5
// baseline (speedup 1.0000x reference)
#include <cuda_runtime.h>
#include <math.h>

namespace {

constexpr int B = 128;
constexpr int N = 2048;
constexpr int E = 32768;
constexpr float INV_SQRT_DH = 0.7071067811865476f;

// Scratch (device globals — no allocations allowed)
__device__ float g_h[B * N * 4];      // node state, 4 MB
__device__ float4 g_qv[B * N];        // per-node q (pre-scaled), 4 MB
__device__ float4 g_kh[B * N];        // per-node h@Wk_top, 4 MB
__device__ float4 g_vh[B * N];        // per-node h@Wv_top, 4 MB
__device__ float g_s[B * N * 2];      // segment sum of exp, 2 MB
__device__ float g_agg[B * N * 4];    // segment sum of p*v, 4 MB

// Weights in constant memory (filled by capturable D2D copies each launch)
__constant__ float cWq[2 * 16];
__constant__ float cWk[2 * 32];
__constant__ float cWv[2 * 32];
__constant__ float cWo[2 * 16];
__constant__ float cbo[2 * 4];
__constant__ float ctw[4];
__constant__ float ctb[4];
__constant__ float cWlin[24];
__constant__ float cblin[2];

// Per-node projections for layer L from state h.
__device__ __forceinline__ void node_project(int L, float4 h,
                                             float4& q, float4& kh, float4& vh) {
    const float* Wq = cWq + L * 16;
    const float* Wk = cWk + L * 32;   // top 4 rows used here
    const float* Wv = cWv + L * 32;
    float qq[4], kk[4], vv[4];
#pragma unroll
    for (int j = 0; j < 4; j++) {
        float a = h.x * Wq[0 * 4 + j];
        a = fmaf(h.y, Wq[1 * 4 + j], a);
        a = fmaf(h.z, Wq[2 * 4 + j], a);
        a = fmaf(h.w, Wq[3 * 4 + j], a);
        qq[j] = a * INV_SQRT_DH;

        float b = h.x * Wk[0 * 4 + j];
        b = fmaf(h.y, Wk[1 * 4 + j], b);
        b = fmaf(h.z, Wk[2 * 4 + j], b);
        b = fmaf(h.w, Wk[3 * 4 + j], b);
        kk[j] = b;

        float c = h.x * Wv[0 * 4 + j];
        c = fmaf(h.y, Wv[1 * 4 + j], c);
        c = fmaf(h.z, Wv[2 * 4 + j], c);
        c = fmaf(h.w, Wv[3 * 4 + j], c);
        vv[j] = c;
    }
    q  = make_float4(qq[0], qq[1], qq[2], qq[3]);
    kh = make_float4(kk[0], kk[1], kk[2], kk[3]);
    vh = make_float4(vv[0], vv[1], vv[2], vv[3]);
}

// ---------------------------------------------------------------------------
// Init: h = x, project layer-0 q/kh/vh, zero s/agg.
// ---------------------------------------------------------------------------
__global__ void __launch_bounds__(256) init_kernel(const float* __restrict__ x) {
    int idx = blockIdx.x * blockDim.x + threadIdx.x;   // 0 .. B*N-1
    float4 xv = reinterpret_cast<const float4*>(x)[idx];
    reinterpret_cast<float4*>(g_h)[idx] = xv;

    float4 q, kh, vh;
    node_project(0, xv, q, kh, vh);
    g_qv[idx] = q;
    g_kh[idx] = kh;
    g_vh[idx] = vh;

    reinterpret_cast<float2*>(g_s)[idx] = make_float2(0.0f, 0.0f);
    reinterpret_cast<float4*>(g_agg)[idx] = make_float4(0.f, 0.f, 0.f, 0.f);
}

// ---------------------------------------------------------------------------
// Edge pass: stage per-batch q/kh/vh tiles (96 KB) in smem; per edge only the
// phi projections remain. Vector-RED p / p*v into global scratch.
// ---------------------------------------------------------------------------
constexpr int BPB = 4;                          // blocks per batch
constexpr int EDGE_THREADS = 512;
constexpr int EDGES_PER_BLOCK = E / BPB;        // 8192
constexpr int EDGE_SMEM = 3 * N * 16;           // 96 KB

template <int L>
__global__ void __launch_bounds__(EDGE_THREADS, 2) edge_pass(
        const int*   __restrict__ edge_index,
        const float* __restrict__ edge_time,
        const float* __restrict__ timestamp) {
    extern __shared__ float4 smem[];
    float4* sq  = smem;           // q tile
    float4* skh = smem + N;       // kh tile
    float4* svh = smem + 2 * N;   // vh tile

    int b     = blockIdx.x >> 2;
    int chunk = blockIdx.x & 3;

    const float4* gq  = g_qv + b * N;
    const float4* gkh = g_kh + b * N;
    const float4* gvh = g_vh + b * N;
#pragma unroll
    for (int i = threadIdx.x; i < N; i += EDGE_THREADS) {
        sq[i]  = gq[i];
        skh[i] = gkh[i];
        svh[i] = gvh[i];
    }
    __syncthreads();

    const float* WkB = cWk + L * 32 + 16;   // bottom 4 rows (phi part)
    const float* WvB = cWv + L * 32 + 16;

    int base = chunk * EDGES_PER_BLOCK;
    const int*   e_src = edge_index + (size_t)b * 2 * E + base;
    const int*   e_dst = e_src + E;
    const float* e_t   = edge_time + (size_t)b * E + base;
    float ts = __ldg(timestamp + b);

    float* s_base   = g_s   + (size_t)b * N * 2;
    float* agg_base = g_agg + (size_t)b * N * 4;

#pragma unroll 4
    for (int e = threadIdx.x; e < EDGES_PER_BLOCK; e += EDGE_THREADS) {
        int src = __ldg(e_src + e);
        int dst = __ldg(e_dst + e);
        float dt = ts - __ldg(e_t + e);

        float phi[4];
#pragma unroll
        for (int j = 0; j < 4; j++) phi[j] = __cosf(fmaf(dt, ctw[j], ctb[j]));

        float4 kh = skh[src];
        float k0 = kh.x, k1 = kh.y, k2 = kh.z, k3 = kh.w;
#pragma unroll
        for (int i = 0; i < 4; i++) {
            k0 = fmaf(phi[i], WkB[i * 4 + 0], k0);
            k1 = fmaf(phi[i], WkB[i * 4 + 1], k1);
            k2 = fmaf(phi[i], WkB[i * 4 + 2], k2);
            k3 = fmaf(phi[i], WkB[i * 4 + 3], k3);
        }

        float4 q = sq[dst];
        float l0 = fmaf(q.x, k0, q.y * k1);
        float l1 = fmaf(q.z, k2, q.w * k3);
        float p0 = __expf(fminf(l0, 80.0f));
        float p1 = __expf(fminf(l1, 80.0f));

        float4 vh = svh[src];
        float v0 = vh.x, v1 = vh.y, v2 = vh.z, v3 = vh.w;
#pragma unroll
        for (int i = 0; i < 4; i++) {
            v0 = fmaf(phi[i], WvB[i * 4 + 0], v0);
            v1 = fmaf(phi[i], WvB[i * 4 + 1], v1);
            v2 = fmaf(phi[i], WvB[i * 4 + 2], v2);
            v3 = fmaf(phi[i], WvB[i * 4 + 3], v3);
        }

        atomicAdd(reinterpret_cast<float2*>(s_base + dst * 2),
                  make_float2(p0, p1));
        atomicAdd(reinterpret_cast<float4*>(agg_base + dst * 4),
                  make_float4(p0 * v0, p0 * v1, p1 * v2, p1 * v3));
    }
}

// ---------------------------------------------------------------------------
// Node update: attn = agg / s, h = relu(h + attn @ Wo + bo).
// LAYER==0: also project layer-1 q/kh/vh and zero s/agg for the next pass.
// ---------------------------------------------------------------------------
template <int LAYER>
__global__ void __launch_bounds__(256) node_kernel() {
    int idx = blockIdx.x * blockDim.x + threadIdx.x;   // 0 .. B*N-1

    float4 agg = reinterpret_cast<const float4*>(g_agg)[idx];
    float2 s   = reinterpret_cast<const float2*>(g_s)[idx];
    float s0 = (s.x == 0.0f) ? 1.0f : s.x;
    float s1 = (s.y == 0.0f) ? 1.0f : s.y;
    float r0 = __frcp_rn(s0);
    float r1 = __frcp_rn(s1);
    float a0 = agg.x * r0, a1 = agg.y * r0;
    float a2 = agg.z * r1, a3 = agg.w * r1;

    const float* Wo = cWo + LAYER * 16;
    const float* bo = cbo + LAYER * 4;

    float4 h = reinterpret_cast<const float4*>(g_h)[idx];
    float hin[4] = {h.x, h.y, h.z, h.w};
    float hn[4];
#pragma unroll
    for (int j = 0; j < 4; j++) {
        float v = hin[j] + bo[j];
        v = fmaf(a0, Wo[0 * 4 + j], v);
        v = fmaf(a1, Wo[1 * 4 + j], v);
        v = fmaf(a2, Wo[2 * 4 + j], v);
        v = fmaf(a3, Wo[3 * 4 + j], v);
        hn[j] = fmaxf(v, 0.0f);
    }
    float4 hnew = make_float4(hn[0], hn[1], hn[2], hn[3]);
    reinterpret_cast<float4*>(g_h)[idx] = hnew;

    if (LAYER == 0) {
        float4 q, kh, vh;
        node_project(1, hnew, q, kh, vh);
        g_qv[idx] = q;
        g_kh[idx] = kh;
        g_vh[idx] = vh;
        reinterpret_cast<float2*>(g_s)[idx] = make_float2(0.0f, 0.0f);
        reinterpret_cast<float4*>(g_agg)[idx] = make_float4(0.f, 0.f, 0.f, 0.f);
    }
}

// ---------------------------------------------------------------------------
// Final head: feats = [h[src_idx], h[dst_idx], cos(ts*w+b)] @ W_lin + b_lin
// ---------------------------------------------------------------------------
__global__ void final_kernel(const int*   __restrict__ src_index,
                             const int*   __restrict__ dst_index,
                             const float* __restrict__ timestamp,
                             float* __restrict__ out) {
    int b = threadIdx.x;
    if (b >= B) return;

    float4 hs = reinterpret_cast<const float4*>(g_h)[b * N + src_index[b]];
    float4 hd = reinterpret_cast<const float4*>(g_h)[b * N + dst_index[b]];
    float ts = timestamp[b];

    float f[12];
    f[0] = hs.x; f[1] = hs.y; f[2] = hs.z; f[3] = hs.w;
    f[4] = hd.x; f[5] = hd.y; f[6] = hd.z; f[7] = hd.w;
#pragma unroll
    for (int j = 0; j < 4; j++) f[8 + j] = cosf(fmaf(ts, ctw[j], ctb[j]));

#pragma unroll
    for (int k = 0; k < 2; k++) {
        float acc = cblin[k];
#pragma unroll
        for (int i = 0; i < 12; i++) acc = fmaf(f[i], cWlin[i * 2 + k], acc);
        out[b * 2 + k] = acc;
    }
}

} // anonymous namespace

extern "C" void kernel_launch(void* const* d_in, const int* in_sizes, int n_in,
                              void* d_out, int out_size) {
    const float* x          = (const float*)d_in[0];
    const int*   edge_index = (const int*)  d_in[1];
    const float* edge_time  = (const float*)d_in[2];
    const float* timestamp  = (const float*)d_in[3];
    const int*   src_index  = (const int*)  d_in[4];
    const int*   dst_index  = (const int*)  d_in[5];
    float* out = (float*)d_out;

    // Allow 96 KB dynamic smem for the edge kernels (idempotent, host-side).
    static bool attr_set = false;
    if (!attr_set) {
        cudaFuncSetAttribute(edge_pass<0>,
            cudaFuncAttributeMaxDynamicSharedMemorySize, EDGE_SMEM);
        cudaFuncSetAttribute(edge_pass<1>,
            cudaFuncAttributeMaxDynamicSharedMemorySize, EDGE_SMEM);
        attr_set = true;
    }

    // Stage all weights into constant memory (device-to-device, capturable).
    cudaMemcpyToSymbolAsync(cWq,   d_in[8],  2 * 16 * 4, 0, cudaMemcpyDeviceToDevice);
    cudaMemcpyToSymbolAsync(cWk,   d_in[9],  2 * 32 * 4, 0, cudaMemcpyDeviceToDevice);
    cudaMemcpyToSymbolAsync(cWv,   d_in[10], 2 * 32 * 4, 0, cudaMemcpyDeviceToDevice);
    cudaMemcpyToSymbolAsync(cWo,   d_in[11], 2 * 16 * 4, 0, cudaMemcpyDeviceToDevice);
    cudaMemcpyToSymbolAsync(cbo,   d_in[12], 2 * 4 * 4,  0, cudaMemcpyDeviceToDevice);
    cudaMemcpyToSymbolAsync(ctw,   d_in[6],  4 * 4,      0, cudaMemcpyDeviceToDevice);
    cudaMemcpyToSymbolAsync(ctb,   d_in[7],  4 * 4,      0, cudaMemcpyDeviceToDevice);
    cudaMemcpyToSymbolAsync(cWlin, d_in[13], 24 * 4,     0, cudaMemcpyDeviceToDevice);
    cudaMemcpyToSymbolAsync(cblin, d_in[14], 2 * 4,      0, cudaMemcpyDeviceToDevice);

    constexpr int NODE_THREADS = 256;
    constexpr int NODE_BLOCKS  = (B * N) / NODE_THREADS;   // 1024
    constexpr int EDGE_BLOCKS  = B * BPB;                  // 512

    init_kernel<<<NODE_BLOCKS, NODE_THREADS>>>(x);

    edge_pass<0><<<EDGE_BLOCKS, EDGE_THREADS, EDGE_SMEM>>>(
        edge_index, edge_time, timestamp);
    node_kernel<0><<<NODE_BLOCKS, NODE_THREADS>>>();

    edge_pass<1><<<EDGE_BLOCKS, EDGE_THREADS, EDGE_SMEM>>>(
        edge_index, edge_time, timestamp);
    node_kernel<1><<<NODE_BLOCKS, NODE_THREADS>>>();

    final_kernel<<<1, 128>>>(src_index, dst_index, timestamp, out);
}

// round 6
// speedup vs baseline: 1.1673x; 1.1673x over previous
#include <cuda_runtime.h>
#include <math.h>

namespace {

constexpr int B = 128;
constexpr int N = 2048;
constexpr int E = 32768;
constexpr float INV_SQRT_DH = 0.7071067811865476f;

// Scratch (device globals — no allocations allowed)
__device__ float g_h[B * N * 4];      // node state, 4 MB
// Interleaved accumulator: per node 8 floats = [agg0..3 | s0 s1 | pad pad]
// Both per-edge REDs hit the same 32B sector.
__device__ float g_acc[B * N * 8];    // 8 MB

// Weights in constant memory (filled by capturable D2D copies each launch)
__constant__ float cWq[2 * 16];
__constant__ float cWk[2 * 32];
__constant__ float cWv[2 * 32];
__constant__ float cWo[2 * 16];
__constant__ float cbo[2 * 4];
__constant__ float ctw[4];
__constant__ float ctb[4];
__constant__ float cWlin[24];
__constant__ float cblin[2];

// ---------------------------------------------------------------------------
// Init: h = x, zero acc.
// ---------------------------------------------------------------------------
__global__ void __launch_bounds__(256) init_kernel(const float* __restrict__ x) {
    int idx = blockIdx.x * blockDim.x + threadIdx.x;   // 0 .. B*N-1
    reinterpret_cast<float4*>(g_h)[idx] =
        reinterpret_cast<const float4*>(x)[idx];
    float4 z = make_float4(0.f, 0.f, 0.f, 0.f);
    reinterpret_cast<float4*>(g_acc)[idx * 2 + 0] = z;
    reinterpret_cast<float4*>(g_acc)[idx * 2 + 1] = z;
}

// ---------------------------------------------------------------------------
// Edge pass: stage this batch's h tile (32 KB) in smem; gather h[src], h[dst]
// from smem; full per-edge math; 2 vector REDs into the interleaved acc.
// Software-pipelined edge loads. 5 blocks/SM via launch_bounds.
// ---------------------------------------------------------------------------
constexpr int BPB = 8;                         // blocks per batch
constexpr int EDGE_THREADS = 256;
constexpr int EDGES_PER_BLOCK = E / BPB;       // 4096
constexpr int EDGE_ITERS = EDGES_PER_BLOCK / EDGE_THREADS;  // 16
constexpr int EDGE_SMEM = N * 16;              // 32 KB (h tile)

template <int L>
__global__ void __launch_bounds__(EDGE_THREADS, 5) edge_pass(
        const int*   __restrict__ edge_index,
        const float* __restrict__ edge_time,
        const float* __restrict__ timestamp) {
    extern __shared__ float4 sh[];   // h tile, N float4

    int b     = blockIdx.x >> 3;
    int chunk = blockIdx.x & 7;

    // Stage h for this batch (coalesced).
    const float4* gh4 = reinterpret_cast<const float4*>(g_h) + b * N;
#pragma unroll
    for (int i = threadIdx.x; i < N; i += EDGE_THREADS) sh[i] = gh4[i];
    __syncthreads();

    const float* Wk = cWk + L * 32;
    const float* Wv = cWv + L * 32;
    const float* Wq = cWq + L * 16;

    int base = chunk * EDGES_PER_BLOCK;
    const int*   e_src = edge_index + (size_t)b * 2 * E + base;
    const int*   e_dst = e_src + E;
    const float* e_t   = edge_time + (size_t)b * E + base;
    float ts = __ldg(timestamp + b);

    float* acc_base = g_acc + (size_t)b * N * 8;

    // Software pipeline: prefetch next iteration's edge tuple.
    int e = threadIdx.x;
    int src = __ldg(e_src + e);
    int dst = __ldg(e_dst + e);
    float t = __ldg(e_t + e);

#pragma unroll
    for (int it = 0; it < EDGE_ITERS; it++) {
        int nsrc = 0, ndst = 0;
        float nt = 0.0f;
        if (it + 1 < EDGE_ITERS) {
            int ne = e + EDGE_THREADS;
            nsrc = __ldg(e_src + ne);
            ndst = __ldg(e_dst + ne);
            nt   = __ldg(e_t + ne);
        }

        float dt = ts - t;
        float4 hs = sh[src];
        float msg[8];
        msg[0] = hs.x; msg[1] = hs.y; msg[2] = hs.z; msg[3] = hs.w;
#pragma unroll
        for (int j = 0; j < 4; j++) msg[4 + j] = __cosf(fmaf(dt, ctw[j], ctb[j]));

        float k[4];
#pragma unroll
        for (int j = 0; j < 4; j++) {
            float acc = msg[0] * Wk[0 * 4 + j];
#pragma unroll
            for (int i = 1; i < 8; i++) acc = fmaf(msg[i], Wk[i * 4 + j], acc);
            k[j] = acc;
        }

        float4 hd = sh[dst];
        float q[4];
#pragma unroll
        for (int j = 0; j < 4; j++) {
            float acc = hd.x * Wq[0 * 4 + j];
            acc = fmaf(hd.y, Wq[1 * 4 + j], acc);
            acc = fmaf(hd.z, Wq[2 * 4 + j], acc);
            acc = fmaf(hd.w, Wq[3 * 4 + j], acc);
            q[j] = acc;
        }

        float l0 = (q[0] * k[0] + q[1] * k[1]) * INV_SQRT_DH;
        float l1 = (q[2] * k[2] + q[3] * k[3]) * INV_SQRT_DH;
        float p0 = __expf(fminf(l0, 80.0f));
        float p1 = __expf(fminf(l1, 80.0f));

        float v[4];
#pragma unroll
        for (int j = 0; j < 4; j++) {
            float acc = msg[0] * Wv[0 * 4 + j];
#pragma unroll
            for (int i = 1; i < 8; i++) acc = fmaf(msg[i], Wv[i * 4 + j], acc);
            v[j] = acc;
        }

        float* nodeacc = acc_base + dst * 8;
        atomicAdd(reinterpret_cast<float4*>(nodeacc),
                  make_float4(p0 * v[0], p0 * v[1], p1 * v[2], p1 * v[3]));
        atomicAdd(reinterpret_cast<float2*>(nodeacc + 4),
                  make_float2(p0, p1));

        src = nsrc; dst = ndst; t = nt;
        e += EDGE_THREADS;
    }
}

// ---------------------------------------------------------------------------
// Node update: attn = agg / s, h = relu(h + attn @ Wo + bo).
// LAYER==0: zero acc for the next pass.
// ---------------------------------------------------------------------------
template <int LAYER>
__global__ void __launch_bounds__(256) node_kernel() {
    int idx = blockIdx.x * blockDim.x + threadIdx.x;   // 0 .. B*N-1

    float4 agg = reinterpret_cast<const float4*>(g_acc)[idx * 2 + 0];
    float4 sv  = reinterpret_cast<const float4*>(g_acc)[idx * 2 + 1];
    float s0 = (sv.x == 0.0f) ? 1.0f : sv.x;
    float s1 = (sv.y == 0.0f) ? 1.0f : sv.y;
    float r0 = __frcp_rn(s0);
    float r1 = __frcp_rn(s1);
    float a0 = agg.x * r0, a1 = agg.y * r0;
    float a2 = agg.z * r1, a3 = agg.w * r1;

    const float* Wo = cWo + LAYER * 16;
    const float* bo = cbo + LAYER * 4;

    float4 h = reinterpret_cast<const float4*>(g_h)[idx];
    float hin[4] = {h.x, h.y, h.z, h.w};
    float hn[4];
#pragma unroll
    for (int j = 0; j < 4; j++) {
        float v = hin[j] + bo[j];
        v = fmaf(a0, Wo[0 * 4 + j], v);
        v = fmaf(a1, Wo[1 * 4 + j], v);
        v = fmaf(a2, Wo[2 * 4 + j], v);
        v = fmaf(a3, Wo[3 * 4 + j], v);
        hn[j] = fmaxf(v, 0.0f);
    }
    reinterpret_cast<float4*>(g_h)[idx] = make_float4(hn[0], hn[1], hn[2], hn[3]);

    if (LAYER == 0) {
        float4 z = make_float4(0.f, 0.f, 0.f, 0.f);
        reinterpret_cast<float4*>(g_acc)[idx * 2 + 0] = z;
        reinterpret_cast<float4*>(g_acc)[idx * 2 + 1] = z;
    }
}

// ---------------------------------------------------------------------------
// Final head: feats = [h[src_idx], h[dst_idx], cos(ts*w+b)] @ W_lin + b_lin
// ---------------------------------------------------------------------------
__global__ void final_kernel(const int*   __restrict__ src_index,
                             const int*   __restrict__ dst_index,
                             const float* __restrict__ timestamp,
                             float* __restrict__ out) {
    int b = threadIdx.x;
    if (b >= B) return;

    float4 hs = reinterpret_cast<const float4*>(g_h)[b * N + src_index[b]];
    float4 hd = reinterpret_cast<const float4*>(g_h)[b * N + dst_index[b]];
    float ts = timestamp[b];

    float f[12];
    f[0] = hs.x; f[1] = hs.y; f[2] = hs.z; f[3] = hs.w;
    f[4] = hd.x; f[5] = hd.y; f[6] = hd.z; f[7] = hd.w;
#pragma unroll
    for (int j = 0; j < 4; j++) f[8 + j] = cosf(fmaf(ts, ctw[j], ctb[j]));

#pragma unroll
    for (int k = 0; k < 2; k++) {
        float acc = cblin[k];
#pragma unroll
        for (int i = 0; i < 12; i++) acc = fmaf(f[i], cWlin[i * 2 + k], acc);
        out[b * 2 + k] = acc;
    }
}

} // anonymous namespace

extern "C" void kernel_launch(void* const* d_in, const int* in_sizes, int n_in,
                              void* d_out, int out_size) {
    const float* x          = (const float*)d_in[0];
    const int*   edge_index = (const int*)  d_in[1];
    const float* edge_time  = (const float*)d_in[2];
    const float* timestamp  = (const float*)d_in[3];
    const int*   src_index  = (const int*)  d_in[4];
    const int*   dst_index  = (const int*)  d_in[5];
    float* out = (float*)d_out;

    // Stage all weights into constant memory (device-to-device, capturable).
    cudaMemcpyToSymbolAsync(cWq,   d_in[8],  2 * 16 * 4, 0, cudaMemcpyDeviceToDevice);
    cudaMemcpyToSymbolAsync(cWk,   d_in[9],  2 * 32 * 4, 0, cudaMemcpyDeviceToDevice);
    cudaMemcpyToSymbolAsync(cWv,   d_in[10], 2 * 32 * 4, 0, cudaMemcpyDeviceToDevice);
    cudaMemcpyToSymbolAsync(cWo,   d_in[11], 2 * 16 * 4, 0, cudaMemcpyDeviceToDevice);
    cudaMemcpyToSymbolAsync(cbo,   d_in[12], 2 * 4 * 4,  0, cudaMemcpyDeviceToDevice);
    cudaMemcpyToSymbolAsync(ctw,   d_in[6],  4 * 4,      0, cudaMemcpyDeviceToDevice);
    cudaMemcpyToSymbolAsync(ctb,   d_in[7],  4 * 4,      0, cudaMemcpyDeviceToDevice);
    cudaMemcpyToSymbolAsync(cWlin, d_in[13], 24 * 4,     0, cudaMemcpyDeviceToDevice);
    cudaMemcpyToSymbolAsync(cblin, d_in[14], 2 * 4,      0, cudaMemcpyDeviceToDevice);

    constexpr int NODE_THREADS = 256;
    constexpr int NODE_BLOCKS  = (B * N) / NODE_THREADS;   // 1024
    constexpr int EDGE_BLOCKS  = B * BPB;                  // 1024

    init_kernel<<<NODE_BLOCKS, NODE_THREADS>>>(x);

    edge_pass<0><<<EDGE_BLOCKS, EDGE_THREADS, EDGE_SMEM>>>(
        edge_index, edge_time, timestamp);
    node_kernel<0><<<NODE_BLOCKS, NODE_THREADS>>>();

    edge_pass<1><<<EDGE_BLOCKS, EDGE_THREADS, EDGE_SMEM>>>(
        edge_index, edge_time, timestamp);
    node_kernel<1><<<NODE_BLOCKS, NODE_THREADS>>>();

    final_kernel<<<1, 128>>>(src_index, dst_index, timestamp, out);
}